// round 7
// baseline (speedup 1.0000x reference)
#include <cuda_runtime.h>

#define Bb 8
#define Tt 800
#define Cc 8
#define Ff 513
#define Aa 320
#define NSYS (Bb*Ff)
#define FB 57        // f per psd block (9*57 = 513 exactly)
#define NFB 9
#define TS 8         // t-chunks
#define TCH 100      // t per chunk
#define ST 5         // t per cp.async stage
#define NSTG (TCH/ST)          // 20
#define TILE_W 60              // f width of data tile (per-row 16B-aligned)
#define NCHROW 15              // 16B chunks per row (60 floats)
#define ROWS_PER_STAGE (Cc*2*ST)          // 80
#define NCHUNK (ROWS_PER_STAGE*NCHROW)    // 1200
#define STAGE_FLOATS (ROWS_PER_STAGE*TILE_W)   // 4800
#define MASK_FLOATS (2*FB*(TCH+1))             // 11514
#define DYN_SMEM ((2*STAGE_FLOATS + MASK_FLOATS)*4)   // 84456 B
#define NTOT ((size_t)Bb*Tt*Cc*Ff)
#define PSTRIDE 37   // 36 psd entries + 1 weight-sum, in float2 units

// ---------------- device scratch ----------------
__device__ float2 g_part2[NSYS*2*TS*PSTRIDE];  // psd partials + weight sums
__device__ float2 g_psd_s[NSYS*64];
__device__ float2 g_psd_n[NSYS*64];
__device__ float  g_e[Bb*Cc];
__device__ float  g_attnpart[64*9*Aa];
__device__ float2 g_wsc[Bb*Cc*Ff];             // conj(ws), layout (b, c, f)

typedef unsigned long long u64;

__device__ __forceinline__ u64 pk2(float lo, float hi){
    u64 r; asm("mov.b64 %0, {%1, %2};" : "=l"(r) : "f"(lo), "f"(hi)); return r;
}
__device__ __forceinline__ void upk2(float &lo, float &hi, u64 v){
    asm("mov.b64 {%0, %1}, %2;" : "=f"(lo), "=f"(hi) : "l"(v));
}
__device__ __forceinline__ void fma2(u64 &d, u64 a, u64 b){
    asm("fma.rn.f32x2 %0, %1, %2, %0;" : "+l"(d) : "l"(a), "l"(b));
}
__device__ __forceinline__ float2 cmul(float2 a, float2 b){
    return make_float2(a.x*b.x - a.y*b.y, a.x*b.y + a.y*b.x);
}
__device__ __forceinline__ float2 csub(float2 a, float2 b){
    return make_float2(a.x - b.x, a.y - b.y);
}
__device__ __forceinline__ float2 cinv(float2 a){
    float d = 1.f/(a.x*a.x + a.y*a.y);
    return make_float2(a.x*d, -a.y*d);
}
__device__ __forceinline__ void cpa16(unsigned dst, const float* src){
    asm volatile("cp.async.cg.shared.global [%0], [%1], 16;" :: "r"(dst), "l"(src));
}

// accumulate one time step into 36 packed accumulators
__device__ __forceinline__ void psd_accum(const float* xr, const float* xi,
                                          float m, u64* acc, float& sumw)
{
    sumw += m;
    u64 av[8], cv[8];
    #pragma unroll
    for (int c = 0; c < 8; c++) {
        av[c] = pk2(xr[c], xi[c]);     // (re, im)
        cv[c] = pk2(xi[c], xr[c]);     // (im, re)
    }
    #pragma unroll
    for (int e = 0; e < 8; e++) {
        float bre = xr[e]*m, bie = xi[e]*m;
        u64 br = pk2(bre,  bre);
        u64 bi = pk2(bie, -bie);
        #pragma unroll
        for (int c = 0; c <= e; c++) {
            int id = (e*(e+1))/2 + c;
            fma2(acc[id], av[c], br);  // re += xr_c*bre, im += xi_c*bre
            fma2(acc[id], cv[c], bi);  // re += xi_c*bie, im -= xr_c*bie
        }
    }
}

// ---------------- K1: fused mask + PSD partials (cp.async pipeline) ------
// grid (9, 8, 8), block 128: fi = tid&63 (f lane), msel = tid>>6
__global__ void __launch_bounds__(128) psd_kernel(
    const float* __restrict__ dre, const float* __restrict__ dimg,
    const float* __restrict__ msk_s, const float* __restrict__ msk_n)
{
    extern __shared__ float sm[];
    float* s_d   = sm;                        // [2][80 rows][60]
    float* s_m   = sm + 2*STAGE_FLOATS;       // [2][FB][TCH+1]

    const int tid  = threadIdx.x;
    const int fi   = tid & 63;
    const int msel = tid >> 6;
    const int b    = blockIdx.y;
    const int f0   = blockIdx.x * FB;
    const int t0   = blockIdx.z * TCH;
    const int fiC  = fi < FB ? fi : FB-1;
    const int f    = f0 + fiC;

    const unsigned sdata = (unsigned)__cvta_generic_to_shared(s_d);

    // Per-row alignment: rowbase mod 4 == c mod 4 (Ff=513 odd, 8 rows/t).
    // Row (t,c) origin = rowbase + f0 - ((c+f0)&3); consumer offset
    // = ((c+f0)&3) + fiC  (<= 59), identical for re and im arrays.

    // ---- prologue: stage 0 in flight beneath the mask phase ----
    {
        for (int i = tid; i < NCHUNK; i += 128) {
            int ch  = i % NCHROW;
            int row = i / NCHROW;
            int tl  = row % ST;
            int cr  = row / ST;
            const float* base = (cr & 1) ? dimg : dre;
            int c = cr >> 1;
            int al = (c + f0) & 3;
            size_t g = ((size_t)(b*Tt + t0 + tl)*Cc + c)*Ff + (f0 - al) + ch*4;
            cpa16(sdata + (unsigned)((row*TILE_W + ch*4)*4), base + g);
        }
        asm volatile("cp.async.commit_group;");
    }

    // ---- mask phase: c-mean of raw masks for the whole (57 f, 100 t) window
    for (int i = tid; i < FB*TCH; i += 128) {
        int fl = i / TCH, t = i - fl*TCH;
        const size_t mb = ((size_t)(b*Ff + f0 + fl)*Cc)*Tt + t0 + t;
        const float* ps = msk_s + mb;
        const float* pn = msk_n + mb;
        float ss = 0.f, sn = 0.f;
        #pragma unroll
        for (int c = 0; c < Cc; c++) {
            ss += fmaxf(ps[c*Tt], 1e-6f);
            sn += fmaxf(pn[c*Tt], 1e-6f);
        }
        s_m[fl*(TCH+1) + t]        = ss * 0.125f;
        s_m[(FB + fl)*(TCH+1) + t] = sn * 0.125f;
    }

    const float* msh = s_m + (msel ? FB*(TCH+1) : 0) + fiC*(TCH+1);

    u64 acc[36];
    #pragma unroll
    for (int i = 0; i < 36; i++) acc[i] = 0ULL;
    float sumw = 0.f;

    for (int s = 0; s < NSTG; s++) {
        if (s + 1 < NSTG) {
            unsigned dbuf = sdata + (unsigned)(((s+1) & 1) * STAGE_FLOATS * 4);
            int tbase = t0 + (s+1)*ST;
            for (int i = tid; i < NCHUNK; i += 128) {
                int ch  = i % NCHROW;
                int row = i / NCHROW;
                int tl  = row % ST;
                int cr  = row / ST;
                const float* base = (cr & 1) ? dimg : dre;
                int c = cr >> 1;
                int al = (c + f0) & 3;
                size_t g = ((size_t)(b*Tt + tbase + tl)*Cc + c)*Ff + (f0 - al) + ch*4;
                cpa16(dbuf + (unsigned)((row*TILE_W + ch*4)*4), base + g);
            }
            asm volatile("cp.async.commit_group;");
            asm volatile("cp.async.wait_group 1;");
        } else {
            asm volatile("cp.async.wait_group 0;");
        }
        __syncthreads();

        const float* buf = s_d + (s & 1) * STAGE_FLOATS;
        #pragma unroll
        for (int tl = 0; tl < ST; tl++) {
            float m = msh[s*ST + tl];
            float xr[8], xi[8];
            #pragma unroll
            for (int c = 0; c < 8; c++) {
                int offc = ((c + f0) & 3) + fiC;
                xr[c] = buf[((c*2    )*ST + tl)*TILE_W + offc];
                xi[c] = buf[((c*2 + 1)*ST + tl)*TILE_W + offc];
            }
            psd_accum(xr, xi, m, acc, sumw);
        }
        __syncthreads();
    }

    if (fi < FB) {
        float2* dst = g_part2 +
            ((size_t)((b*Ff + f)*2 + msel)*TS + blockIdx.z)*PSTRIDE;
        #pragma unroll
        for (int i = 0; i < 36; i++) {
            float lo, hi; upk2(lo, hi, acc[i]);
            dst[i] = make_float2(lo, hi);
        }
        dst[36] = make_float2(sumw, 0.f);
    }
}

// ---------------- K1b: reduce partials, normalize, Hermitian expand ------
__global__ void reduce_kernel()
{
    const int sys = blockIdx.x;
    const int tid = threadIdx.x;
    const int msel = tid >> 6;
    const int ce = tid & 63;
    const int c = ce >> 3, e = ce & 7;
    const int hi = c > e ? c : e;
    const int lo = c > e ? e : c;
    const int id = (hi*(hi+1))/2 + lo;

    const float2* base = g_part2 + ((size_t)(sys*2 + msel)*TS)*PSTRIDE;
    float2 v = make_float2(0.f, 0.f);
    float sw = 0.f;
    #pragma unroll
    for (int ts = 0; ts < TS; ts++) {
        float2 p = base[ts*PSTRIDE + id];
        v.x += p.x; v.y += p.y;
        sw  += base[ts*PSTRIDE + 36].x;
    }
    float inv = 1.f/(sw + 1e-15f);
    v.x *= inv; v.y *= inv;
    if (c > e) v.y = -v.y;
    (msel ? g_psd_n : g_psd_s)[(size_t)sys*64 + ce] = v;
}

// ---------------- K2a: attention partial GEMV ----------------------------
__global__ void attn1_kernel(const float* __restrict__ mlp_w)
{
    __shared__ float feat[64];
    const int tid = threadIdx.x;
    const int bc  = blockIdx.y;
    const int b   = bc >> 3;
    const int c   = bc & 7;
    const int fbeg = blockIdx.x * 64;
    const int L = min(64, Ff - fbeg);

    if (tid < L) {
        int f = fbeg + tid;
        const float2* p = g_psd_s + (size_t)(b*Ff + f)*64 + c*8;
        float sr = 0.f, si = 0.f;
        #pragma unroll
        for (int e = 0; e < 8; e++) { float2 v = p[e]; sr += v.x; si += v.y; }
        float2 d = p[c]; sr -= d.x; si -= d.y;
        sr *= (1.f/7.f); si *= (1.f/7.f);
        feat[tid] = sqrtf(sr*sr + si*si);
    }
    __syncthreads();

    float a0 = 0.f, a1 = 0.f;
    const float* wp = mlp_w + (size_t)fbeg*Aa + tid;
    int j = 0;
    #pragma unroll 8
    for (; j + 1 < L; j += 2) {
        a0 += feat[j]   * wp[(size_t)j*Aa];
        a1 += feat[j+1] * wp[(size_t)(j+1)*Aa];
    }
    if (j < L) a0 += feat[j] * wp[(size_t)j*Aa];
    g_attnpart[(bc*9 + blockIdx.x)*Aa + tid] = a0 + a1;
}

__global__ void attn2_kernel(const float* __restrict__ mlp_b,
                             const float* __restrict__ gvw,
                             const float* __restrict__ gvb)
{
    __shared__ float red[Aa];
    const int tid = threadIdx.x;
    const int bc  = blockIdx.x;
    float s = mlp_b[tid];
    #pragma unroll
    for (int ch = 0; ch < 9; ch++) s += g_attnpart[(bc*9 + ch)*Aa + tid];
    red[tid] = tanhf(s) * gvw[tid];
    __syncthreads();
    if (tid < 160) red[tid] += red[tid+160]; __syncthreads();
    if (tid <  80) red[tid] += red[tid+ 80]; __syncthreads();
    if (tid <  40) red[tid] += red[tid+ 40]; __syncthreads();
    if (tid <  20) red[tid] += red[tid+ 20]; __syncthreads();
    if (tid <  10) red[tid] += red[tid+ 10]; __syncthreads();
    if (tid == 0) {
        float t = 0.f;
        #pragma unroll
        for (int i = 0; i < 10; i++) t += red[i];
        g_e[bc] = t + gvb[0];
    }
}

// ---------------- K3: MVDR solve, register rows + shfl broadcast ---------
__global__ void __launch_bounds__(256) solve_kernel()
{
    const unsigned FULL = 0xffffffffu;
    const int tid  = threadIdx.x;
    const int warp = tid >> 5, lane = tid & 31;
    const int g = lane >> 3, r = lane & 7;
    const int bl = lane & 24;

    int sys = blockIdx.x*32 + warp*4 + g;
    bool ok = sys < NSYS;
    int sc = ok ? sys : NSYS-1;
    int b = sc / Ff, f = sc - b*Ff;

    float2 A[8], S[8];
    #pragma unroll
    for (int j = 0; j < 8; j++) {
        A[j] = g_psd_n[(size_t)sc*64 + r*8 + j];
        S[j] = g_psd_s[(size_t)sc*64 + r*8 + j];
    }
    A[r].x += 1e-15f;

    float u[8];
    {
        float mx = -1e30f;
        #pragma unroll
        for (int j = 0; j < 8; j++) { u[j] = 2.f*g_e[b*8+j]; mx = fmaxf(mx, u[j]); }
        float s = 0.f;
        #pragma unroll
        for (int j = 0; j < 8; j++) { u[j] = expf(u[j]-mx); s += u[j]; }
        float is = 1.f/s;
        #pragma unroll
        for (int j = 0; j < 8; j++) u[j] *= is;
    }

    #pragma unroll
    for (int k = 0; k < 7; k++) {
        float2 pa[8], ps[8];
        #pragma unroll
        for (int j = 0; j < 8; j++) {
            pa[j].x = __shfl_sync(FULL, A[j].x, bl + k);
            pa[j].y = __shfl_sync(FULL, A[j].y, bl + k);
            ps[j].x = __shfl_sync(FULL, S[j].x, bl + k);
            ps[j].y = __shfl_sync(FULL, S[j].y, bl + k);
        }
        float2 ip = cinv(pa[k]);
        if (r > k) {
            float2 fac = cmul(A[k], ip);
            #pragma unroll
            for (int j = 0; j < 8; j++) {
                A[j] = csub(A[j], cmul(fac, pa[j]));
                S[j] = csub(S[j], cmul(fac, ps[j]));
            }
        }
    }
    #pragma unroll
    for (int k = 7; k >= 0; k--) {
        if (r == k) {
            float2 ip = cinv(A[k]);
            #pragma unroll
            for (int j = 0; j < 8; j++) S[j] = cmul(S[j], ip);
        }
        float2 ps[8];
        #pragma unroll
        for (int j = 0; j < 8; j++) {
            ps[j].x = __shfl_sync(FULL, S[j].x, bl + k);
            ps[j].y = __shfl_sync(FULL, S[j].y, bl + k);
        }
        if (r < k) {
            float2 fac = A[k];
            #pragma unroll
            for (int j = 0; j < 8; j++) S[j] = csub(S[j], cmul(fac, ps[j]));
        }
    }

    float2 tr = make_float2(1e-15f, 0.f);
    #pragma unroll
    for (int j = 0; j < 8; j++) {
        tr.x += __shfl_sync(FULL, S[j].x, bl + j);
        tr.y += __shfl_sync(FULL, S[j].y, bl + j);
    }
    float2 it = cinv(tr);
    float wr = 0.f, wi = 0.f;
    #pragma unroll
    for (int c = 0; c < 8; c++) { wr += S[c].x*u[c]; wi += S[c].y*u[c]; }
    float2 w = cmul(make_float2(wr, wi), it);
    if (ok) g_wsc[(size_t)(b*8+r)*Ff + f] = make_float2(w.x, -w.y);
}

// ---------------- K4: enhanced output ------------------------------------
__global__ void enh_kernel(const float* __restrict__ dre,
                           const float* __restrict__ dimg,
                           float2* __restrict__ out)
{
    __shared__ float2 wsh[8*Ff];
    const int tid = threadIdx.x;
    const int b  = blockIdx.y;
    const int t0 = blockIdx.x * 8;

    for (int i = tid; i < 8*Ff; i += 256)
        wsh[i] = g_wsc[(size_t)b*8*Ff + i];
    __syncthreads();

    for (int tt = 0; tt < 8; tt++) {
        size_t bt = (size_t)b*Tt + t0 + tt;
        const float* pr = dre  + bt*Cc*Ff;
        const float* pi = dimg + bt*Cc*Ff;
        for (int f = tid; f < Ff; f += 256) {
            float er = 0.f, ei = 0.f;
            #pragma unroll
            for (int c = 0; c < 8; c++) {
                float dr = pr[c*Ff + f];
                float di = pi[c*Ff + f];
                float2 w = wsh[c*Ff + f];
                er += w.x*dr - w.y*di;
                ei += w.x*di + w.y*dr;
            }
            out[bt*Ff + f] = make_float2(er, ei);
        }
    }
}

// ---------------- launch --------------------------------------------------
extern "C" void kernel_launch(void* const* d_in, const int* in_sizes, int n_in,
                              void* d_out, int out_size)
{
    const float* dre   = (const float*)d_in[0];
    const float* dimg  = (const float*)d_in[1];
    const float* ms    = (const float*)d_in[2];
    const float* mn    = (const float*)d_in[3];
    const float* mlp_w = (const float*)d_in[4];
    const float* mlp_b = (const float*)d_in[5];
    const float* gvw   = (const float*)d_in[6];
    const float* gvb   = (const float*)d_in[7];
    (void)in_sizes; (void)n_in; (void)out_size;

    cudaFuncSetAttribute(psd_kernel,
        cudaFuncAttributeMaxDynamicSharedMemorySize, DYN_SMEM);

    psd_kernel<<<dim3(NFB, Bb, TS), 128, DYN_SMEM>>>(dre, dimg, ms, mn);
    reduce_kernel<<<NSYS, 128>>>();
    attn1_kernel<<<dim3(9, 64), Aa>>>(mlp_w);
    attn2_kernel<<<64, Aa>>>(mlp_b, gvw, gvb);
    solve_kernel<<<(NSYS+31)/32, 256>>>();
    enh_kernel<<<dim3(Tt/8, Bb), 256>>>(dre, dimg, (float2*)d_out);
}